// round 14
// baseline (speedup 1.0000x reference)
#include <cuda_runtime.h>

#define S 26
#define D 7
#define DA 11
#define V 29
#define NT 384
#define TRI (S*(S+1)/2)   // 351
#define LOG2E 1.4426950408889634f

__device__ __forceinline__ float ex2(float x) {
    float y; asm("ex2.approx.f32 %0, %1;" : "=f"(y) : "f"(x)); return y;
}
__device__ __forceinline__ float rcpa(float x) {
    float y; asm("rcp.approx.f32 %0, %1;" : "=f"(y) : "f"(x)); return y;
}

__global__ __launch_bounds__(NT, 1)
void bes_transformer_kernel(
    const int*   __restrict__ x,
    const float* __restrict__ emb_table,
    const float* __restrict__ pos,
    const float* __restrict__ wk0, const float* __restrict__ bk0,
    const float* __restrict__ wq0, const float* __restrict__ bq0,
    const float* __restrict__ wv0, const float* __restrict__ bv0,
    const float* __restrict__ wf0, const float* __restrict__ bf0,
    const float* __restrict__ wk1, const float* __restrict__ bk1,
    const float* __restrict__ wq1, const float* __restrict__ bq1,
    const float* __restrict__ wv1, const float* __restrict__ bv1,
    const float* __restrict__ wf1, const float* __restrict__ bf1,
    const float* __restrict__ wout, const float* __restrict__ bout,
    float* __restrict__ out)
{
    __shared__ float h[S][D];
    __shared__ float k[S][DA];
    __shared__ float q[S][DA];    // pre-scaled by log2(e)
    __shared__ float v[S][DA];
    __shared__ float att[S][S];   // lower triangle valid; upper garbage
    __shared__ float res[S][DA];
    __shared__ float inv_s[S];

    const int t = threadIdx.x;

    // packed lower-triangle coords (t < TRI)
    int tr = 0, tc = 0;
    if (t < TRI) {
        tr = (int)((sqrtf(8.f * (float)t + 1.f) - 1.f) * 0.5f);
        if (t < tr * (tr + 1) / 2) tr--;
        if (t >= (tr + 1) * (tr + 2) / 2) tr++;
        tc = t - tr * (tr + 1) / 2;
    }

    // ===== entry-time register prefetch of per-thread weight roles =========
    // QKV role: t < 286, row a = t % 11.
    float pk0[D], pq0[D], pv0[D], pk1[D], pq1[D], pv1[D];
    float bk0r = 0.f, bq0r = 0.f, bv0r = 0.f, bk1r = 0.f, bq1r = 0.f, bv1r = 0.f;
    if (t < S * DA) {
        int a = t % DA;
        #pragma unroll
        for (int d = 0; d < D; d++) {
            pk0[d] = wk0[a * D + d];
            pq0[d] = wq0[a * D + d];
            pv0[d] = wv0[a * D + d];
            pk1[d] = wk1[a * D + d];
            pq1[d] = wq1[a * D + d];
            pv1[d] = wv1[a * D + d];
        }
        bk0r = bk0[a]; bq0r = bq0[a]; bv0r = bv0[a];
        bk1r = bk1[a]; bq1r = bq1[a]; bv1r = bv1[a];
    }
    // proj role: t < 182, row d = t % 7.
    float pf0[DA], pf1[DA];
    float bf0r = 0.f, bf1r = 0.f;
    if (t < S * D) {
        int d = t % D;
        #pragma unroll
        for (int a = 0; a < DA; a++) {
            pf0[a] = wf0[d * DA + a];
            pf1[a] = wf1[d * DA + a];
        }
        bf0r = bf0[d]; bf1r = bf1[d];
    }
    // logits role: items t and t+NT of the 754 = S*V outputs.
    float po0[D], po1[D];
    float bo0 = 0.f, bo1 = 0.f;
    {
        int v0i = t % V;
        bo0 = bout[v0i];
        #pragma unroll
        for (int d = 0; d < D; d++) po0[d] = wout[v0i * D + d];
        if (t + NT < S * V) {
            int v1i = (t + NT) % V;
            bo1 = bout[v1i];
            #pragma unroll
            for (int d = 0; d < D; d++) po1[d] = wout[v1i * D + d];
        }
    }

    // ---- stage 1: fused embedding + QKV layer 0 ----
    if (t < S * DA) {
        int s = t / DA, a = t % DA;
        int xv = x[s];
        float sk = bk0r, sq = bq0r, sv = bv0r;
        #pragma unroll
        for (int d = 0; d < D; d++) {
            float hv = emb_table[xv * D + d] + pos[s * D + d];
            sk += hv * pk0[d];
            sq += hv * pq0[d];
            sv += hv * pv0[d];
        }
        k[s][a] = sk; q[s][a] = sq * LOG2E; v[s][a] = sv;
    }
    __syncthreads();

    // ---- stage 2: scores 0 (packed triangle, ex2) ----
    if (t < TRI) {
        float sum = 0.f;
        #pragma unroll
        for (int a = 0; a < DA; a++) sum += q[tr][a] * k[tc][a];
        att[tr][tc] = ex2(sum);
    }
    __syncthreads();

    // ---- stage 3: AV0 + normalize ----
    if (t < S * DA) {
        int s = t / DA, a = t % DA;
        float sum = 0.f, dot = 0.f;
        for (int c = 0; c <= s; c++) {
            float e = att[s][c];
            sum += e;
            dot += e * v[c][a];
        }
        res[s][a] = dot * rcpa(sum);
    }
    __syncthreads();

    // ---- stage 4: proj0 -> h ----
    if (t < S * D) {
        int s = t / D;
        float r = bf0r;
        #pragma unroll
        for (int a = 0; a < DA; a++) r += res[s][a] * pf0[a];
        h[s][t % D] = r;
    }
    __syncthreads();

    // ---- stage 5: QKV layer 1 ----
    if (t < S * DA) {
        int s = t / DA, a = t % DA;
        float sk = bk1r, sq = bq1r, sv = bv1r;
        #pragma unroll
        for (int d = 0; d < D; d++) {
            float hv = h[s][d];
            sk += hv * pk1[d];
            sq += hv * pq1[d];
            sv += hv * pv1[d];
        }
        k[s][a] = sk; q[s][a] = sq * LOG2E; v[s][a] = sv;
    }
    __syncthreads();

    // ---- stage 6: scores 1 ----
    if (t < TRI) {
        float sum = 0.f;
        #pragma unroll
        for (int a = 0; a < DA; a++) sum += q[tr][a] * k[tc][a];
        att[tr][tc] = ex2(sum);
    }
    __syncthreads();

    // ---- stage 7: AV1 + normalize ----
    if (t < S * DA) {
        int s = t / DA, a = t % DA;
        float sum = 0.f, dot = 0.f;
        for (int c = 0; c <= s; c++) {
            float e = att[s][c];
            sum += e;
            dot += e * v[c][a];
        }
        float iv = rcpa(sum);
        res[s][a] = dot * iv;
        if (a == 0) inv_s[s] = iv;
    }
    __syncthreads();

    // ---- stage 8: proj1 -> h; att rows to output in parallel ----
    if (t < S * D) {
        int s = t / D;
        float r = bf1r;
        #pragma unroll
        for (int a = 0; a < DA; a++) r += res[s][a] * pf1[a];
        h[s][t % D] = r;
    }
    for (int i = t; i < S * S; i += NT) {
        int rr = i / S, cc = i % S;
        out[S * V + i] = (cc <= rr) ? att[rr][cc] * inv_s[rr] : 0.f;
    }
    __syncthreads();

    // ---- stage 9: logits with prefetched wout rows (pure smem+FMA) ----
    {
        int s = t / V;
        float r = bo0;
        #pragma unroll
        for (int d = 0; d < D; d++) r += h[s][d] * po0[d];
        out[t] = r;
    }
    if (t + NT < S * V) {
        int s = (t + NT) / V;
        float r = bo1;
        #pragma unroll
        for (int d = 0; d < D; d++) r += h[s][d] * po1[d];
        out[t + NT] = r;
    }
}

extern "C" void kernel_launch(void* const* d_in, const int* in_sizes, int n_in,
                              void* d_out, int out_size)
{
    bes_transformer_kernel<<<1, NT>>>(
        (const int*)  d_in[0],   // x
        (const float*)d_in[1],   // emb_table
        (const float*)d_in[2],   // pos
        (const float*)d_in[3],  (const float*)d_in[4],   // w_k0, b_k0
        (const float*)d_in[5],  (const float*)d_in[6],   // w_q0, b_q0
        (const float*)d_in[7],  (const float*)d_in[8],   // w_v0, b_v0
        (const float*)d_in[9],  (const float*)d_in[10],  // w_f0, b_f0
        (const float*)d_in[11], (const float*)d_in[12],  // w_k1, b_k1
        (const float*)d_in[13], (const float*)d_in[14],  // w_q1, b_q1
        (const float*)d_in[15], (const float*)d_in[16],  // w_v1, b_v1
        (const float*)d_in[17], (const float*)d_in[18],  // w_f1, b_f1
        (const float*)d_in[19], (const float*)d_in[20],  // w_out, b_out
        (float*)d_out);
}